// round 8
// baseline (speedup 1.0000x reference)
#include <cuda_runtime.h>
#include <cstdint>

#define T_LEN  16384
#define BATCH  10
#define DDIM   3
#define HDIM   4
#define NITER  10
#define NCHAIN (NITER*BATCH)   // 100
#define NGATE  16
#define PFD    8               // prefetch depth (steps)

// ---------------- device scratch (static: no allocation allowed) ----------------
__device__ float g_W2[NITER*DDIM*NGATE];                       // zx & 0.5-scale folded
__device__ float g_U2[NITER*HDIM*NGATE];                       // zh & 0.5-scale folded
__device__ float g_xproj[(size_t)NCHAIN*T_LEN*NGATE + PFD*NGATE]; // padded: clamp-free prefetch
__device__ float g_scratch[(size_t)T_LEN*NCHAIN*16];           // [t][chain][16]: o0-3,h0-3,c0-3,pad

// ---------------- helpers ----------------
__device__ __forceinline__ float tanh_ap(float x) {
    float y; asm("tanh.approx.f32 %0, %1;" : "=f"(y) : "f"(x)); return y;
}

// ---------------- 1) fold masks/scales into W2, U2 ----------------
// gate order k = gate*4 + unit, gates: 0=i 1=f 2=o 3=g. Scale 0.5 for i,f,o
// (sigmoid(a) = 0.5*tanh(a/2)+0.5), 1.0 for g.
__global__ void setup_k(const float* __restrict__ zx, const float* __restrict__ zh,
                        const float* __restrict__ Wi, const float* __restrict__ Ui,
                        const float* __restrict__ Wf, const float* __restrict__ Uf,
                        const float* __restrict__ Wo, const float* __restrict__ Uo,
                        const float* __restrict__ Wg, const float* __restrict__ Ug) {
    int tid = blockIdx.x * blockDim.x + threadIdx.x;
    if (tid < NITER*DDIM*NGATE) {                  // W2: zx * W * scale
        int k = tid % NGATE, d = (tid / NGATE) % DDIM, it = tid / (NGATE*DDIM);
        int gate = k >> 2, u = k & 3;
        const float* W = (gate == 0) ? Wi : (gate == 1) ? Wf : (gate == 2) ? Wo : Wg;
        float s = (gate < 3) ? 0.5f : 1.0f;
        g_W2[tid] = zx[it*DDIM + d] * W[d*HDIM + u] * s;
    }
    if (tid < NITER*HDIM*NGATE) {                  // U2: zh * U * scale
        int k = tid % NGATE, j = (tid / NGATE) % HDIM, it = tid / (NGATE*HDIM);
        int gate = k >> 2, u = k & 3;
        const float* U = (gate == 0) ? Ui : (gate == 1) ? Uf : (gate == 2) ? Uo : Ug;
        float s = (gate < 3) ? 0.5f : 1.0f;
        g_U2[tid] = zh[it*HDIM + j] * U[j*HDIM + u] * s;
    }
}

// ---------------- 2) precompute xproj[chain][t][16] ----------------
__global__ void __launch_bounds__(256) xproj_k(const float* __restrict__ x) {
    int tid = blockIdx.x * blockDim.x + threadIdx.x;     // chain-major, t fastest
    int t = tid % T_LEN;
    int chain = tid / T_LEN;
    if (chain >= NCHAIN) return;
    int it = chain / BATCH, b = chain % BATCH;
    const float* xr = x + ((size_t)t*BATCH + b)*DDIM;
    float x0 = xr[0], x1 = xr[1], x2 = xr[2];
    const float* W = g_W2 + it*DDIM*NGATE;
    float v[NGATE];
#pragma unroll
    for (int k = 0; k < NGATE; k++)
        v[k] = x0*W[k] + x1*W[NGATE + k] + x2*W[2*NGATE + k];
    float4* out = (float4*)(g_xproj + ((size_t)chain*T_LEN + t)*NGATE);
    out[0] = make_float4(v[0],  v[1],  v[2],  v[3]);
    out[1] = make_float4(v[4],  v[5],  v[6],  v[7]);
    out[2] = make_float4(v[8],  v[9],  v[10], v[11]);
    out[3] = make_float4(v[12], v[13], v[14], v[15]);
}

// ---------------- 3) serial recurrence: 16 lanes per chain, gates on lanes ----------------
// lane k = gate*4 + unit. Every lane redundantly computes (c,h) for unit u=k&3
// via 4 computed-src gather shfls, so every lane has a valid value to store:
// branch-free single STG.32 per lane per step. All addressing is reg+imm.
__global__ void __launch_bounds__(16, 1) lstm_k() {
    const int lane  = threadIdx.x;      // 0..15
    const int chain = blockIdx.x;
    const int u = lane & 3;
    const int g = lane >> 2;
    const unsigned FULL = 0xFFFFu;

    // per-lane U column (zh mask & sigmoid half-scale already folded)
    const float* Ub = g_U2 + (chain / BATCH)*HDIM*NGATE;
    const float u0 = Ub[0*NGATE + lane];
    const float u1 = Ub[1*NGATE + lane];
    const float u2 = Ub[2*NGATE + lane];
    const float u3 = Ub[3*NGATE + lane];

    const float* xp  = g_xproj + (size_t)chain*T_LEN*NGATE + lane;
    const float* xld = xp + (size_t)PFD*NGATE;       // prefetch cursor (padded array)
    float*       stp = g_scratch + (size_t)chain*16 + lane;

    float h = 0.f, c = 0.f;

    float xbuf[PFD];
#pragma unroll
    for (int p = 0; p < PFD; p++) xbuf[p] = xp[(size_t)p*NGATE];

    for (int t = 0; t < T_LEN; t += PFD) {
#pragma unroll
        for (int p = 0; p < PFD; p++) {
            float xv = xbuf[p];
            xbuf[p] = xld[p*NGATE];                  // reg+imm; ~1000 cyc lookahead

            // broadcast h0..h3 (lanes 0-3 hold them; all lanes hold h_{k&3})
            float h0 = __shfl_sync(FULL, h, 0, 16);
            float h1 = __shfl_sync(FULL, h, 1, 16);
            float h2 = __shfl_sync(FULL, h, 2, 16);
            float h3 = __shfl_sync(FULL, h, 3, 16);

            // a_k = xp_k + sum_j h_j * U2[j][k]  (balanced tree, depth 12)
            float pa = fmaf(h0, u0, xv);
            float pm = h3*u3;
            float pb = fmaf(h2, u2, pm);
            pa = fmaf(h1, u1, pa);
            float a = pa + pb;

            float tv = tanh_ap(a);                   // 1 MUFU: all 16 gates

            // gather all 4 gates of unit u (computed src lanes, independent)
            float ti = __shfl_sync(FULL, tv,      u, 16);
            float tf = __shfl_sync(FULL, tv,  4 + u, 16);
            float to = __shfl_sync(FULL, tv,  8 + u, 16);
            float tg = __shfl_sync(FULL, tv, 12 + u, 16);

            // sigmoid(x) = 0.5*tanh(x/2)+0.5 (the /2 is folded into W2/U2)
            float iv = fmaf(ti, 0.5f, 0.5f);
            float fv = fmaf(tf, 0.5f, 0.5f);
            float ov = fmaf(to, 0.5f, 0.5f);

            c = fmaf(fv, c, iv*tg);
            float tc = tanh_ap(c);                   // 1 MUFU: 4 cells (redundant x4)
            h = ov*tc;

            // branch-free store: lane g=0 -> o_u, g=1 -> h_u, g=2 -> c_u, g=3 dummy
            float sval = (g == 0) ? ov : (g == 1) ? h : c;
            stp[p*(NCHAIN*16)] = sval;               // one coalesced STG.32, reg+imm
        }
        xld += PFD*NGATE;
        stp += PFD*(NCHAIN*16);
    }
}

// ---------------- 4) deterministic mean over the 10 MC iterations ----------------
__global__ void __launch_bounds__(256) reduce_k(float* __restrict__ out) {
    int tid = blockIdx.x * blockDim.x + threadIdx.x;
    if (tid >= T_LEN*BATCH) return;
    int t = tid / BATCH, b = tid % BATCH;
    // chain row for (it,b): g_scratch[t][it*BATCH+b][16] -> 4 float4: o4,h4,c4,pad
    const float4* base = (const float4*)(g_scratch + (size_t)t*NCHAIN*16) + (size_t)b*4;
    float4 so = make_float4(0.f,0.f,0.f,0.f);
    float4 sh = so, sc4 = so;
#pragma unroll
    for (int it = 0; it < NITER; it++) {
        const float4* row = base + (size_t)it*BATCH*4;
        float4 o4 = row[0], h4 = row[1], c4 = row[2];
        so.x += o4.x;  so.y += o4.y;  so.z += o4.z;  so.w += o4.w;
        sh.x += h4.x;  sh.y += h4.y;  sh.z += h4.z;  sh.w += h4.w;
        sc4.x += c4.x; sc4.y += c4.y; sc4.z += c4.z; sc4.w += c4.w;
    }
    const size_t TEN4 = (size_t)T_LEN*BATCH;         // in float4 units (HDIM=4)
    float4* out4 = (float4*)out;
    size_t idx = (size_t)t*BATCH + b;
    out4[idx]          = make_float4(0.1f*so.x,  0.1f*so.y,  0.1f*so.z,  0.1f*so.w);
    out4[TEN4 + idx]   = make_float4(0.1f*sh.x,  0.1f*sh.y,  0.1f*sh.z,  0.1f*sh.w);
    out4[2*TEN4 + idx] = make_float4(0.1f*sc4.x, 0.1f*sc4.y, 0.1f*sc4.z, 0.1f*sc4.w);
}

// ---------------- launch ----------------
extern "C" void kernel_launch(void* const* d_in, const int* in_sizes, int n_in,
                              void* d_out, int out_size) {
    const float* input = (const float*)d_in[0];
    const float* zx    = (const float*)d_in[1];
    const float* zh    = (const float*)d_in[2];
    const float* Wi    = (const float*)d_in[3];
    const float* Ui    = (const float*)d_in[4];
    const float* Wf    = (const float*)d_in[5];
    const float* Uf    = (const float*)d_in[6];
    const float* Wo    = (const float*)d_in[7];
    const float* Uo    = (const float*)d_in[8];
    const float* Wg    = (const float*)d_in[9];
    const float* Ug    = (const float*)d_in[10];
    float* out = (float*)d_out;

    setup_k<<<1, 1024>>>(zx, zh, Wi, Ui, Wf, Uf, Wo, Uo, Wg, Ug);
    xproj_k<<<(NCHAIN*T_LEN + 255)/256, 256>>>(input);
    lstm_k<<<NCHAIN, 16>>>();
    reduce_k<<<(T_LEN*BATCH + 255)/256, 256>>>(out);
}